// round 17
// baseline (speedup 1.0000x reference)
#include <cuda_runtime.h>
#include <cuda_bf16.h>
#include <cstdint>
#include <cfloat>

#define BATCH 4
#define SEQ   2048
#define DMODEL 128
#define DLOW  16
#define NEGV  (-1e9f)
#define SCALE 0.25f
#define NQB   64            // q-blocks per batch (SEQ/32)

// ---- scratch (static __device__, no allocations) ----
__device__ float g_S[BATCH * SEQ * SEQ];          // 64 MB: exp(corrected scores)
__device__ float g_qlow[BATCH * SEQ * DLOW];
__device__ float g_klowT[BATCH * DLOW * SEQ];
__device__ float g_c[BATCH * SEQ];                // exp(correction score)
__device__ float g_part[NQB][BATCH * SEQ];        // column-sum partials
__device__ float g_Zadj[BATCH * SEQ];
__device__ __nv_bfloat16 g_VhT[BATCH * DMODEL * SEQ];   // (V*w)^T hi, [b][d][k]
__device__ __nv_bfloat16 g_VlT[BATCH * DMODEL * SEQ];   // (V*w)^T lo

// ============================================================
// K1: projections. One block (64 threads) per (b, position).
// Also zeroes g_Zadj.
// ============================================================
__global__ void proj_kernel(const float* __restrict__ q, const float* __restrict__ k,
                            const float* __restrict__ Wql, const float* __restrict__ bql,
                            const float* __restrict__ Wkl, const float* __restrict__ bkl,
                            const float* __restrict__ Wqh, const float* __restrict__ bqh,
                            const float* __restrict__ Wkh, const float* __restrict__ bkh)
{
    int p = blockIdx.x;
    int b = p >> 11, i = p & (SEQ - 1);
    __shared__ float qs[DMODEL], ks[DMODEL];
    __shared__ float qh[DLOW], kh[DLOW];
    int t = threadIdx.x;
    if (t == 1) g_Zadj[p] = 0.f;
    {
        float2 qv = *(const float2*)&q[p * DMODEL + t * 2];
        qs[t * 2] = qv.x; qs[t * 2 + 1] = qv.y;
        float2 kv = *(const float2*)&k[p * DMODEL + t * 2];
        ks[t * 2] = kv.x; ks[t * 2 + 1] = kv.y;
    }
    __syncthreads();
    int j = t & 15;
    int which = t >> 4;
    const float* W; const float* bias; const float* src;
    if (which == 0)      { W = Wql; bias = bql; src = qs; }
    else if (which == 1) { W = Wkl; bias = bkl; src = ks; }
    else if (which == 2) { W = Wqh; bias = bqh; src = qs; }
    else                 { W = Wkh; bias = bkh; src = ks; }
    float acc = bias[j];
    #pragma unroll 16
    for (int d0 = 0; d0 < DMODEL; d0++)
        acc = fmaf(src[d0], W[d0 * DLOW + j], acc);
    if (which == 0)      g_qlow[p * DLOW + j] = acc;
    else if (which == 1) g_klowT[(b * DLOW + j) * SEQ + i] = acc;
    else if (which == 2) qh[j] = acc;
    else                 kh[j] = acc;
    __syncthreads();
    if (t == 0) {
        float c = 0.f;
        #pragma unroll
        for (int jj = 0; jj < DLOW; jj++) c = fmaf(qh[jj], kh[jj], c);
        g_c[p] = __expf(c * SCALE);
    }
}

// ============================================================
// K2: FUSED scores + top-8.
// Block = 32 q-rows x full k (16 tiles of 128). Writes exp(S),
// column partial sums, keeps chunk maxima in smem; then does
// warp-per-row threshold top-8 on its own L2-hot rows + scatter.
// ============================================================
__global__ void __launch_bounds__(256) scores_topk_kernel(const int* __restrict__ valid_lens)
{
    int b  = blockIdx.y;
    int q0 = blockIdx.x * 32;
    __shared__ float qT[DLOW][32];
    __shared__ float kS[DLOW][128];
    __shared__ float redsm[8][128];
    __shared__ float chmax[32][17];        // [row][chunk], padded
    __shared__ int   vlsm[SEQ];            // pre-clamped valid_lens for this batch
    __shared__ float cV[8][64];
    __shared__ int   cI[8][64];
    __shared__ int   cnt[8];
    int t = threadIdx.x, lane = t & 31, ty = t >> 5;

    // qT: 32 rows x 16
    if (t < 128) {
        int row = t >> 2, j0 = (t & 3) * 4;
        const float4 v = *(const float4*)&g_qlow[(b * SEQ + q0 + row) * DLOW + j0];
        qT[j0 + 0][row] = v.x; qT[j0 + 1][row] = v.y;
        qT[j0 + 2][row] = v.z; qT[j0 + 3][row] = v.w;
    }
    // valid_lens, clamped — FULL SEQ coverage (2 passes of 4 per thread)
    #pragma unroll
    for (int r = 0; r < 2; r++) {
        int idx = (t + r * 256) * 4;
        int4 vv = *(const int4*)&valid_lens[b * SEQ + idx];
        vlsm[idx + 0] = min(max(vv.x, 0), SEQ - 1);
        vlsm[idx + 1] = min(max(vv.y, 0), SEQ - 1);
        vlsm[idx + 2] = min(max(vv.z, 0), SEQ - 1);
        vlsm[idx + 3] = min(max(vv.w, 0), SEQ - 1);
    }

    int m0 = ty * 4, n0 = lane * 4;        // thread tile: 4q x 4k

    for (int kt = 0; kt < 16; kt++) {
        int k0 = kt * 128;
        __syncthreads();                   // protect kS reuse (and first-iter loads)
        {
            int row = t >> 5, c0 = (t & 31) * 4;
            #pragma unroll
            for (int r = 0; r < DLOW; r += 8)
                *(float4*)&kS[row + r][c0] =
                    *(const float4*)&g_klowT[(b * DLOW + row + r) * SEQ + k0 + c0];
        }
        __syncthreads();

        float acc[4][4];
        #pragma unroll
        for (int i = 0; i < 4; i++)
            #pragma unroll
            for (int jj = 0; jj < 4; jj++) acc[i][jj] = 0.f;
        #pragma unroll
        for (int j = 0; j < DLOW; j++) {
            float a[4];
            *(float4*)&a[0] = *(const float4*)&qT[j][m0];
            float4 bv = *(const float4*)&kS[j][n0];
            #pragma unroll
            for (int i = 0; i < 4; i++) {
                acc[i][0] = fmaf(a[i], bv.x, acc[i][0]);
                acc[i][1] = fmaf(a[i], bv.y, acc[i][1]);
                acc[i][2] = fmaf(a[i], bv.z, acc[i][2]);
                acc[i][3] = fmaf(a[i], bv.w, acc[i][3]);
            }
        }
        int vl[4];
        #pragma unroll
        for (int jj = 0; jj < 4; jj++) vl[jj] = vlsm[k0 + n0 + jj];

        float cs[4] = {0.f, 0.f, 0.f, 0.f};
        #pragma unroll
        for (int i = 0; i < 4; i++) {
            int qrow = q0 + m0 + i;
            float4 o; float* po = (float*)&o;
            float rm = -FLT_MAX;
            #pragma unroll
            for (int jj = 0; jj < 4; jj++) {
                float v = acc[i][jj] * SCALE;
                if (vl[jj] == qrow) v += NEGV;
                float e = __expf(v);
                po[jj] = e;
                cs[jj] += e;
                rm = fmaxf(rm, e);
            }
            *(float4*)&g_S[(b * SEQ + qrow) * SEQ + k0 + n0] = o;
            #pragma unroll
            for (int off = 16; off > 0; off >>= 1)
                rm = fmaxf(rm, __shfl_xor_sync(0xffffffffu, rm, off));
            if (lane == 0) chmax[m0 + i][kt] = rm;
        }
        #pragma unroll
        for (int jj = 0; jj < 4; jj++) redsm[ty][n0 + jj] = cs[jj];
        __syncthreads();
        if (t < 128) {
            float s = 0.f;
            #pragma unroll
            for (int r = 0; r < 8; r++) s += redsm[r][t];
            g_part[blockIdx.x][b * SEQ + k0 + t] = s;
        }
    }
    __syncthreads();

    // ---- top-8 phase: warp ty handles its own rows m0..m0+3 (L2-hot) ----
    #pragma unroll 1
    for (int rr = 0; rr < 4; rr++) {
        int lrow = m0 + rr;
        float* Srow = &g_S[(b * SEQ + q0 + lrow) * SEQ];

        float cm0 = (lane < 16) ? chmax[lrow][lane] : -FLT_MAX;
        float a = cm0, T = cm0;
        #pragma unroll
        for (int it = 0; it < 8; it++) {
            float m = a;
            #pragma unroll
            for (int off = 16; off > 0; off >>= 1)
                m = fmaxf(m, __shfl_xor_sync(0xffffffffu, m, off));
            T = m;
            unsigned ba = __ballot_sync(0xffffffffu, a == m);
            if (lane == (int)(__ffs(ba) - 1)) a = -FLT_MAX;
        }
        unsigned chunkmask = __ballot_sync(0xffffffffu, cm0 >= T) & 0xffffu;

        if (lane == 0) cnt[ty] = 0;
        __syncwarp();
        unsigned mrem = chunkmask;
        while (mrem) {
            int c = __ffs(mrem) - 1;
            mrem &= mrem - 1;
            int off = c * 128 + lane * 4;
            float4 x = *(const float4*)&Srow[off];
            float m4 = fmaxf(fmaxf(x.x, x.y), fmaxf(x.z, x.w));
            if (m4 >= T) {
                const float* xv = (const float*)&x;
                #pragma unroll
                for (int jj = 0; jj < 4; jj++) {
                    if (xv[jj] >= T) {
                        int p = atomicAdd(&cnt[ty], 1);
                        if (p < 64) { cV[ty][p] = xv[jj]; cI[ty][p] = off + jj; }
                    }
                }
            }
        }
        __syncwarp();
        int nc = cnt[ty];

        int   chI[8];
        float chV[8];

        if (nc <= 64) {
            #pragma unroll 1
            for (int it = 0; it < 8; it++) {
                float bv = -FLT_MAX; int bi = 0x7fffffff;
                for (int p = lane; p < nc; p += 32) {
                    float cv = cV[ty][p]; int ci = cI[ty][p];
                    if (cv > bv || (cv == bv && ci < bi)) { bv = cv; bi = ci; }
                }
                #pragma unroll
                for (int off = 16; off > 0; off >>= 1) {
                    float ov = __shfl_xor_sync(0xffffffffu, bv, off);
                    int   oi = __shfl_xor_sync(0xffffffffu, bi, off);
                    if (ov > bv || (ov == bv && oi < bi)) { bv = ov; bi = oi; }
                }
                for (int p = lane; p < nc; p += 32)
                    if (cI[ty][p] == bi) cV[ty][p] = -FLT_MAX;
                chI[it] = bi; chV[it] = bv;
            }
        } else {
            // exact slow path: global rescan with chosen-exclusion (rare/never)
            #pragma unroll 1
            for (int it = 0; it < 8; it++) {
                float bv = -FLT_MAX; int bi = 0x7fffffff;
                for (int p = lane; p < SEQ; p += 32) {
                    bool skip = false;
                    #pragma unroll 8
                    for (int x = 0; x < 8; x++)
                        if (x < it && chI[x] == p) skip = true;
                    if (skip) continue;
                    float cv = Srow[p];
                    if (cv > bv || (cv == bv && p < bi)) { bv = cv; bi = p; }
                }
                #pragma unroll
                for (int off = 16; off > 0; off >>= 1) {
                    float ov = __shfl_xor_sync(0xffffffffu, bv, off);
                    int   oi = __shfl_xor_sync(0xffffffffu, bi, off);
                    if (ov > bv || (ov == bv && oi < bi)) { bv = ov; bi = oi; }
                }
                chI[it] = bi; chV[it] = bv;
            }
        }

        if (lane == 0) {
            #pragma unroll
            for (int it = 0; it < 8; it++) {
                int bi = chI[it];
                float ec = g_c[b * SEQ + bi];
                Srow[bi] = ec;
                atomicAdd(&g_Zadj[b * SEQ + bi], ec - chV[it]);
            }
        }
    }
}

// ============================================================
// K3: (V*w)^T split into bf16 hi/lo; finalize (w = 1/Z) fused.
// ============================================================
__global__ void vconv_kernel(const float* __restrict__ V)
{
    int b = blockIdx.y, k0 = blockIdx.x * 32;
    __shared__ float vs[32][129];
    __shared__ float wsh[32];
    int t = threadIdx.x;
    if (t < 32) {
        int idx = b * SEQ + k0 + t;
        float z = g_Zadj[idx];
        #pragma unroll
        for (int s = 0; s < NQB; s++) z += g_part[s][idx];
        wsh[t] = 1.0f / z;
    }
    __syncthreads();
    {
        int r = t >> 3, c0 = (t & 7) * 16;
        float wk = wsh[r];
        #pragma unroll
        for (int qd = 0; qd < 4; qd++) {
            float4 vv = *(const float4*)&V[(b * SEQ + k0 + r) * DMODEL + c0 + qd * 4];
            vs[r][c0 + qd * 4 + 0] = vv.x * wk;
            vs[r][c0 + qd * 4 + 1] = vv.y * wk;
            vs[r][c0 + qd * 4 + 2] = vv.z * wk;
            vs[r][c0 + qd * 4 + 3] = vv.w * wk;
        }
    }
    __syncthreads();
    int d = t >> 1, kh = (t & 1) * 16;
    uint4 hq[2], lq[2];
    __nv_bfloat162* hp = (__nv_bfloat162*)hq;
    __nv_bfloat162* lp = (__nv_bfloat162*)lq;
    #pragma unroll
    for (int i = 0; i < 8; i++) {
        float x0 = vs[kh + 2 * i][d], x1 = vs[kh + 2 * i + 1][d];
        __nv_bfloat16 h0 = __float2bfloat16(x0), h1 = __float2bfloat16(x1);
        hp[i] = __halves2bfloat162(h0, h1);
        lp[i] = __halves2bfloat162(__float2bfloat16(x0 - __bfloat162float(h0)),
                                   __float2bfloat16(x1 - __bfloat162float(h1)));
    }
    __nv_bfloat16* dsth = &g_VhT[(b * DMODEL + d) * SEQ + k0 + kh];
    *(uint4*)dsth = hq[0];
    *((uint4*)dsth + 1) = hq[1];
    __nv_bfloat16* dstl = &g_VlT[(b * DMODEL + d) * SEQ + k0 + kh];
    *(uint4*)dstl = lq[0];
    *((uint4*)dstl + 1) = lq[1];
}

// ============================================================
// K4: tensor-core output GEMM with split-bf16 compensation (R13 config).
// ============================================================
#define PST   40
#define P_SZ  (64 * PST)
#define V_SZ  (128 * PST)
#define BUFE  (2 * P_SZ + 2 * V_SZ)
#define MMA_SMEM (2 * BUFE * 2)

#define MMA_OP(c, a, bb) \
    asm volatile("mma.sync.aligned.m16n8k16.row.col.f32.bf16.bf16.f32 " \
        "{%0,%1,%2,%3}, {%4,%5,%6,%7}, {%8,%9}, {%0,%1,%2,%3};" \
        : "+f"((c)[0]), "+f"((c)[1]), "+f"((c)[2]), "+f"((c)[3]) \
        : "r"((a)[0]), "r"((a)[1]), "r"((a)[2]), "r"((a)[3]), \
          "r"((bb)[0]), "r"((bb)[1]))

__global__ void __launch_bounds__(256) out_gemm_mma(float* __restrict__ out)
{
    extern __shared__ __nv_bfloat16 smb[];
    int b = blockIdx.y, q0 = blockIdx.x * 64;
    int t = threadIdx.x, lane = t & 31, w = t >> 5;
    int g = lane >> 2, tq = lane & 3;
    int wm = w >> 2, wn = w & 3;

    const float* Sbase = &g_S[(b * SEQ + q0) * SEQ];
    const __nv_bfloat16* VhB = &g_VhT[b * DMODEL * SEQ];
    const __nv_bfloat16* VlB = &g_VlT[b * DMODEL * SEQ];

    int s_q = t >> 2, s_k = (t & 3) * 8;
    int v_d = t >> 1, v_k = (t & 1) * 16;

    float acc[2][4][4];
    #pragma unroll
    for (int mt = 0; mt < 2; mt++)
        #pragma unroll
        for (int nt = 0; nt < 4; nt++)
            #pragma unroll
            for (int x = 0; x < 4; x++) acc[mt][nt][x] = 0.f;

    float4 sP[2]; uint4 sVh[2], sVl[2];

    auto LOADG = [&](int kt) {
        sP[0] = *(const float4*)&Sbase[s_q * SEQ + kt + s_k];
        sP[1] = *(const float4*)&Sbase[s_q * SEQ + kt + s_k + 4];
        const uint4* ph = (const uint4*)&VhB[v_d * SEQ + kt + v_k];
        sVh[0] = ph[0]; sVh[1] = ph[1];
        const uint4* pl = (const uint4*)&VlB[v_d * SEQ + kt + v_k];
        sVl[0] = pl[0]; sVl[1] = pl[1];
    };
    auto STORES = [&](int buf) {
        __nv_bfloat16* Ph = smb + buf * BUFE;
        __nv_bfloat16* Pl = Ph + P_SZ;
        __nv_bfloat16* Vh = Ph + 2 * P_SZ;
        __nv_bfloat16* Vl = Vh + V_SZ;
        float f[8];
        *(float4*)&f[0] = sP[0]; *(float4*)&f[4] = sP[1];
        uint4 hq, lq;
        __nv_bfloat162* hp = (__nv_bfloat162*)&hq;
        __nv_bfloat162* lp = (__nv_bfloat162*)&lq;
        #pragma unroll
        for (int i = 0; i < 4; i++) {
            __nv_bfloat16 h0 = __float2bfloat16(f[2 * i]);
            __nv_bfloat16 h1 = __float2bfloat16(f[2 * i + 1]);
            hp[i] = __halves2bfloat162(h0, h1);
            lp[i] = __halves2bfloat162(
                __float2bfloat16(f[2 * i] - __bfloat162float(h0)),
                __float2bfloat16(f[2 * i + 1] - __bfloat162float(h1)));
        }
        *(uint4*)&Ph[s_q * PST + s_k] = hq;
        *(uint4*)&Pl[s_q * PST + s_k] = lq;
        *(uint4*)&Vh[v_d * PST + v_k]     = sVh[0];
        *(uint4*)&Vh[v_d * PST + v_k + 8] = sVh[1];
        *(uint4*)&Vl[v_d * PST + v_k]     = sVl[0];
        *(uint4*)&Vl[v_d * PST + v_k + 8] = sVl[1];
    };
    auto COMPUTE = [&](int buf) {
        const __nv_bfloat16* Ph = smb + buf * BUFE;
        const __nv_bfloat16* Pl = Ph + P_SZ;
        const __nv_bfloat16* Vh = Ph + 2 * P_SZ;
        const __nv_bfloat16* Vl = Vh + V_SZ;
        #pragma unroll
        for (int ks = 0; ks < 32; ks += 16) {
            uint32_t ah[2][4], al[2][4];
            #pragma unroll
            for (int mt = 0; mt < 2; mt++) {
                int r = (wm * 32 + mt * 16 + g) * PST + ks + 2 * tq;
                ah[mt][0] = *(const uint32_t*)&Ph[r];
                ah[mt][1] = *(const uint32_t*)&Ph[r + 8 * PST];
                ah[mt][2] = *(const uint32_t*)&Ph[r + 8];
                ah[mt][3] = *(const uint32_t*)&Ph[r + 8 * PST + 8];
                al[mt][0] = *(const uint32_t*)&Pl[r];
                al[mt][1] = *(const uint32_t*)&Pl[r + 8 * PST];
                al[mt][2] = *(const uint32_t*)&Pl[r + 8];
                al[mt][3] = *(const uint32_t*)&Pl[r + 8 * PST + 8];
            }
            uint32_t bh[4][2], bl[4][2];
            #pragma unroll
            for (int nt = 0; nt < 4; nt++) {
                int r = (wn * 32 + nt * 8 + g) * PST + ks + 2 * tq;
                bh[nt][0] = *(const uint32_t*)&Vh[r];
                bh[nt][1] = *(const uint32_t*)&Vh[r + 8];
                bl[nt][0] = *(const uint32_t*)&Vl[r];
                bl[nt][1] = *(const uint32_t*)&Vl[r + 8];
            }
            #pragma unroll
            for (int mt = 0; mt < 2; mt++)
                #pragma unroll
                for (int nt = 0; nt < 4; nt++) {
                    MMA_OP(acc[mt][nt], ah[mt], bh[nt]);
                    MMA_OP(acc[mt][nt], ah[mt], bl[nt]);
                    MMA_OP(acc[mt][nt], al[mt], bh[nt]);
                }
        }
    };

    LOADG(0);
    STORES(0);
    __syncthreads();
    const int NKT = SEQ / 32;
    for (int kt_i = 0; kt_i < NKT; kt_i++) {
        if (kt_i + 1 < NKT) LOADG((kt_i + 1) * 32);
        COMPUTE(kt_i & 1);
        if (kt_i + 1 < NKT) STORES((kt_i & 1) ^ 1);
        __syncthreads();
    }

    #pragma unroll
    for (int mt = 0; mt < 2; mt++)
        #pragma unroll
        for (int nt = 0; nt < 4; nt++) {
            int qq = q0 + wm * 32 + mt * 16 + g;
            int dd = wn * 32 + nt * 8 + 2 * tq;
            *(float2*)&out[(b * SEQ + qq) * DMODEL + dd] =
                make_float2(acc[mt][nt][0], acc[mt][nt][1]);
            *(float2*)&out[(b * SEQ + qq + 8) * DMODEL + dd] =
                make_float2(acc[mt][nt][2], acc[mt][nt][3]);
        }
}

// ============================================================
extern "C" void kernel_launch(void* const* d_in, const int* in_sizes, int n_in,
                              void* d_out, int out_size)
{
    const float* queries = (const float*)d_in[0];
    const float* keys    = (const float*)d_in[1];
    const float* values  = (const float*)d_in[2];
    const int*   vlens   = (const int*)  d_in[3];
    const float* Wql     = (const float*)d_in[4];
    const float* bql     = (const float*)d_in[5];
    const float* Wkl     = (const float*)d_in[6];
    const float* bkl     = (const float*)d_in[7];
    const float* Wqh     = (const float*)d_in[8];
    const float* bqh     = (const float*)d_in[9];
    const float* Wkh     = (const float*)d_in[10];
    const float* bkh     = (const float*)d_in[11];
    float* out = (float*)d_out;

    static bool attr_set = false;
    if (!attr_set) {
        cudaFuncSetAttribute(out_gemm_mma,
                             cudaFuncAttributeMaxDynamicSharedMemorySize, MMA_SMEM);
        attr_set = true;
    }

    proj_kernel<<<BATCH * SEQ, 64>>>(queries, keys, Wql, bql, Wkl, bkl,
                                     Wqh, bqh, Wkh, bkh);
    scores_topk_kernel<<<dim3(NQB, BATCH), 256>>>(vlens);
    vconv_kernel<<<dim3(SEQ / 32, BATCH), 256>>>(values);
    out_gemm_mma<<<dim3(SEQ / 64, BATCH), 256, MMA_SMEM>>>(out);
}